// round 7
// baseline (speedup 1.0000x reference)
#include <cuda_runtime.h>

#define NATOM 100000
#define MNBR  12
#define AF    64
#define BF    41
#define TWOA  128
#define NM    (NATOM*MNBR)          // 1200000
#define NMF   ((double)NM)
#define NF    ((double)NATOM)
#define EPSBN 1e-5
#define GEMM_GRID (NM/96)           // 12500

// ---- dynamic smem layout (bytes) ----
#define BT_PAD    104
#define OFF_WP    0                              // float4 Wp[41*32]        = 20992
#define OFF_BT    20992                          // float bT[41*104]        = 17056
#define OFF_BRAW  (OFF_BT + BF*BT_PAD*4)         // 38048; float braw[96*41]= 15744
#define OFF_PWS   (OFF_BRAW + 96*BF*4)           // 53792; float PWs[96*128]= 49152
#define OFF_SWS   (OFF_PWS + 96*TWOA*4)          // 102944; float SWs[8*128]= 4096
#define OFF_IDX   (OFF_SWS + 8*TWOA*4)           // 107040; int idxS[96]
#define SMEM_BYTES (OFF_IDX + 96*4)              // 107424  (x2 = 214.8 KB <= 228 KB)
#define OFF_RED   OFF_BRAW                       // reductions overlay braw (dead post-transpose)

typedef unsigned long long ull;

// ---------------- scratch (device globals; no allocations) ----------------
__device__ float  d_SW[(size_t)NATOM*TWOA];      // atom @ W[0:64] + bias
__device__ float  d_PW[(size_t)NATOM*TWOA];      // atom @ W[64:128]
__device__ float  d_gated[(size_t)NM*TWOA];      // staged gated (614 MB)
__device__ float  d_summed[(size_t)NATOM*AF];
__device__ double d_s1[TWOA], d_q1[TWOA];
__device__ double d_s2[AF],   d_q2[AF];
__device__ float  d_g1[TWOA], d_h1[TWOA];
__device__ float  d_g2[AF],   d_h2[AF];
__device__ unsigned d_c1, d_c2;

// ---------------- helpers ----------------
__device__ __forceinline__ void ffma2(ull &d, ull a, ull b) {
    asm("fma.rn.f32x2 %0, %1, %2, %0;" : "+l"(d) : "l"(a), "l"(b));
}
__device__ __forceinline__ ull packdup(float x) {
    ull r; asm("mov.b64 %0, {%1, %1};" : "=l"(r) : "f"(x)); return r;
}
__device__ __forceinline__ float2 unpk(ull v) {
    float2 r; asm("mov.b64 {%0, %1}, %2;" : "=f"(r.x), "=f"(r.y) : "l"(v)); return r;
}
__device__ __forceinline__ float sigmoidf_(float x) {
    return __fdividef(1.0f, 1.0f + __expf(-x));
}
__device__ __forceinline__ float softplusf_(float x) {
    float e = __expf(-fabsf(x));
    return fmaxf(x, 0.0f) + __logf(1.0f + e);
}
__device__ __forceinline__ void cpasync16(void* dst_smem, const void* src) {
    unsigned s = (unsigned)__cvta_generic_to_shared(dst_smem);
    asm volatile("cp.async.cg.shared.global [%0], [%1], 16;" :: "r"(s), "l"(src) : "memory");
}
#define CP_COMMIT() asm volatile("cp.async.commit_group;" ::: "memory")
#define CP_WAIT(n)  asm volatile("cp.async.wait_group %0;" :: "n"(n) : "memory")

// ---------------- kInitA / kInitB ----------------
__global__ void kInitA() {
    int t = threadIdx.x;
    if (t < TWOA) { d_s1[t] = 0.0; d_q1[t] = 0.0; }
    if (t == 0)   d_c1 = 0u;
}
__global__ void kInitB() {
    int t = threadIdx.x;
    if (t < AF) { d_s2[t] = 0.0; d_q2[t] = 0.0; }
    if (t == 0) d_c2 = 0u;
}

// ---------------- kA: SW = atom@W1 + b, PW = atom@W2 ----------------
__global__ void __launch_bounds__(256) kA(const float* __restrict__ atom,
                                          const float* __restrict__ W,
                                          const float* __restrict__ bias) {
    __shared__ __align__(16) float at[64][132];
    int t = threadIdx.x;
    int aBase = blockIdx.x * 128;
    int aCount = NATOM - aBase; if (aCount > 128) aCount = 128;

    float wreg[64];
    const float* wp = (t < 128) ? (W + t) : (W + 64 * TWOA + (t - 128));
    #pragma unroll
    for (int k = 0; k < 64; k++) wreg[k] = wp[k * TWOA];
    float bj = (t < 128) ? bias[t] : 0.0f;

    for (int idx = t; idx < 128 * 64; idx += 256) {
        int a = idx >> 6, k = idx & 63;
        at[k][a] = (a < aCount) ? atom[(size_t)(aBase + a) * AF + k] : 0.0f;
    }
    __syncthreads();

    float* dst = (t < 128) ? d_SW : d_PW;
    int j = t & 127;

    for (int c = 0; c < 16; c++) {
        int a0 = c * 8;
        ull acc[4] = {0ull, 0ull, 0ull, 0ull};
        #pragma unroll
        for (int k = 0; k < 64; k++) {
            ull wk = packdup(wreg[k]);
            const ull* ap = (const ull*)&at[k][a0];
            ffma2(acc[0], ap[0], wk);
            ffma2(acc[1], ap[1], wk);
            ffma2(acc[2], ap[2], wk);
            ffma2(acc[3], ap[3], wk);
        }
        #pragma unroll
        for (int q = 0; q < 4; q++) {
            float2 v = unpk(acc[q]);
            int a = a0 + 2 * q;
            if (a < aCount)     dst[(size_t)(aBase + a)     * TWOA + j] = v.x + bj;
            if (a + 1 < aCount) dst[(size_t)(aBase + a + 1) * TWOA + j] = v.y + bj;
        }
    }
}

// ============ kGemmStore: gated = bond@W3 + SW + PW_gather; store gated; BN1 stats ============
// block = 96 rows (8 atoms) x 128 cols, 384 threads = 12 warps, warp owns 8 rows.
// lane owns cols {2l,2l+1, 64+2l,64+2l+1}. PW rows + SW rows prefetched via cp.async.
__global__ void __launch_bounds__(384, 2) kGemmStore(const float* __restrict__ bond,
                                                     const int*   __restrict__ nidx,
                                                     const float* __restrict__ W,
                                                     const float* __restrict__ sc,
                                                     const float* __restrict__ of) {
    extern __shared__ __align__(16) char sm[];
    float4* Wp   = (float4*)(sm + OFF_WP);
    float*  bT   = (float*) (sm + OFF_BT);
    float*  braw = (float*) (sm + OFF_BRAW);
    float*  PWs  = (float*) (sm + OFF_PWS);
    float*  SWs  = (float*) (sm + OFF_SWS);
    int*    idxS = (int*)   (sm + OFF_IDX);
    __shared__ int sLast;

    int t = threadIdx.x, lane = t & 31, w = t >> 5;   // w in 0..11
    int blk = blockIdx.x;
    int r0 = 8 * w;
    int cA = 2 * lane;

    // (1) bond tile raw -> smem (async, group A): 984 16B-chunks
    {
        const float* bsrc = bond + (size_t)blk * 96 * BF;
        #pragma unroll
        for (int i = 0; i < 3; i++) {
            int c = t + 384 * i;
            if (c < 96 * BF / 4) cpasync16(braw + c * 4, bsrc + c * 4);
        }
    }
    CP_COMMIT();

    // (2) neighbor indices
    if (t < 96) idxS[t] = nidx[blk * 96 + t];
    __syncthreads();   // idxS visible

    // (3) group B: SW rows (contiguous 4KB) + PW gather (96 rows x 32 chunks)
    if (t < 256) cpasync16(SWs + t * 4, d_SW + (size_t)blk * 8 * TWOA + t * 4);
    #pragma unroll
    for (int i = 0; i < 8; i++) {
        int id = t + 384 * i;
        int row = id >> 5, ch = id & 31;
        cpasync16(&PWs[row * TWOA + ch * 4],
                  &d_PW[(size_t)idxS[row] * TWOA + ch * 4]);
    }
    CP_COMMIT();

    // (4) per-lane packed weights: Wp[k*32+l] = {W3[k][2l],W3[k][2l+1],W3[k][64+2l],W3[k][64+2l+1]}
    #pragma unroll
    for (int i = 0; i < 4; i++) {
        int id = t + 384 * i;
        if (id < BF * 32) {
            int k = id >> 5, l = id & 31;
            const float* wr = W + TWOA * TWOA + k * TWOA;
            float2 a  = *(const float2*)&wr[2 * l];
            float2 b2 = *(const float2*)&wr[64 + 2 * l];
            Wp[id] = make_float4(a.x, a.y, b2.x, b2.y);
        }
    }

    // (5) wait bond; transpose braw[r][k] -> bT[k][r]
    CP_WAIT(1);
    __syncthreads();
    #pragma unroll
    for (int i = 0; i < 11; i++) {
        int id = t + 384 * i;
        if (id < 96 * BF) {
            int k = id / 96, r = id - 96 * k;
            bT[k * BT_PAD + r] = braw[r * BF + k];
        }
    }
    __syncthreads();

    // (6) GEMM: acc[p] = row-pair (r0+2p, r0+2p+1), 4 cols each
    ull acc[4][4];
    #pragma unroll
    for (int p = 0; p < 4; p++)
        #pragma unroll
        for (int u = 0; u < 4; u++) acc[p][u] = 0ull;

    #pragma unroll
    for (int k = 0; k < BF; k++) {
        float4 wv = Wp[k * 32 + lane];
        ull w0 = packdup(wv.x), w1 = packdup(wv.y);
        ull w2 = packdup(wv.z), w3 = packdup(wv.w);
        const char* brow = (const char*)(bT + k * BT_PAD + r0);
        ulonglong2 q0 = *(const ulonglong2*)(brow);
        ulonglong2 q1 = *(const ulonglong2*)(brow + 16);
        ull bv0 = q0.x, bv1 = q0.y, bv2 = q1.x, bv3 = q1.y;
        ffma2(acc[0][0], bv0, w0); ffma2(acc[0][1], bv0, w1); ffma2(acc[0][2], bv0, w2); ffma2(acc[0][3], bv0, w3);
        ffma2(acc[1][0], bv1, w0); ffma2(acc[1][1], bv1, w1); ffma2(acc[1][2], bv1, w2); ffma2(acc[1][3], bv1, w3);
        ffma2(acc[2][0], bv2, w0); ffma2(acc[2][1], bv2, w1); ffma2(acc[2][2], bv2, w2); ffma2(acc[2][3], bv2, w3);
        ffma2(acc[3][0], bv3, w0); ffma2(acc[3][1], bv3, w1); ffma2(acc[3][2], bv3, w2); ffma2(acc[3][3], bv3, w3);
    }

    // (7) wait PW/SW prefetch; epilogue: assemble gated, store (streaming), accumulate stats
    CP_WAIT(0);
    __syncthreads();
    float* gbase = d_gated + (size_t)(blk * 96 + r0) * TWOA;

    float ls0 = 0, ls1 = 0, ls2 = 0, ls3 = 0;
    float lq0 = 0, lq1 = 0, lq2 = 0, lq3 = 0;
    #pragma unroll
    for (int p = 0; p < 4; p++) {
        float2 aA0 = unpk(acc[p][0]), aA1 = unpk(acc[p][1]);
        float2 aB0 = unpk(acc[p][2]), aB1 = unpk(acc[p][3]);
        #pragma unroll
        for (int s = 0; s < 2; s++) {
            int rr = r0 + 2 * p + s;          // local row 0..95
            int aLoc = rr / 12;               // local atom 0..7
            const float* swr = SWs + aLoc * TWOA;
            const float* pr  = PWs + rr * TWOA;
            float2 swA = *(const float2*)(swr + cA);
            float2 swB = *(const float2*)(swr + 64 + cA);
            float2 pA  = *(const float2*)(pr + cA);
            float2 pB  = *(const float2*)(pr + 64 + cA);
            float v0 = (s ? aA0.y : aA0.x) + swA.x + pA.x;
            float v1 = (s ? aA1.y : aA1.x) + swA.y + pA.y;
            float v2 = (s ? aB0.y : aB0.x) + swB.x + pB.x;
            float v3 = (s ? aB1.y : aB1.x) + swB.y + pB.y;
            float2 gA; gA.x = v0; gA.y = v1;
            float2 gB; gB.x = v2; gB.y = v3;
            __stcs((float2*)(gbase + (size_t)(2 * p + s) * TWOA + cA), gA);
            __stcs((float2*)(gbase + (size_t)(2 * p + s) * TWOA + 64 + cA), gB);
            ls0 += v0; lq0 += v0 * v0;
            ls1 += v1; lq1 += v1 * v1;
            ls2 += v2; lq2 += v2 * v2;
            ls3 += v3; lq3 += v3 * v3;
        }
    }
    float* redS = (float*)(sm + OFF_RED);
    float* redQ = redS + 12 * TWOA;
    redS[w * TWOA + cA] = ls0;       redS[w * TWOA + cA + 1] = ls1;
    redS[w * TWOA + 64 + cA] = ls2;  redS[w * TWOA + 64 + cA + 1] = ls3;
    redQ[w * TWOA + cA] = lq0;       redQ[w * TWOA + cA + 1] = lq1;
    redQ[w * TWOA + 64 + cA] = lq2;  redQ[w * TWOA + 64 + cA + 1] = lq3;
    __syncthreads();
    if (t < TWOA) {
        float s = 0.0f, q = 0.0f;
        #pragma unroll
        for (int w2 = 0; w2 < 12; w2++) { s += redS[w2 * TWOA + t]; q += redQ[w2 * TWOA + t]; }
        atomicAdd(&d_s1[t], (double)s);
        atomicAdd(&d_q1[t], (double)q);
    }
    __syncthreads();
    if (t == 0) {
        __threadfence();
        unsigned old = atomicAdd(&d_c1, 1u);
        sLast = (old == GEMM_GRID - 1) ? 1 : 0;
    }
    __syncthreads();
    if (sLast && t < TWOA) {
        double s = *((volatile double*)&d_s1[t]);
        double q = *((volatile double*)&d_q1[t]);
        double mean = s / NMF;
        double var  = q / NMF - mean * mean;
        float g = sc[t] * (float)(1.0 / sqrt(var + EPSBN));
        d_g1[t] = g;
        d_h1[t] = of[t] - (float)mean * g;
    }
}

// ---------------- kC: stream gated -> BN1 affine -> sig*softplus -> sum_M; BN2 stats + fin2 ----
// block = 8 warps = 8 atoms; lane j owns output cols 2j, 2j+1
__global__ void __launch_bounds__(256) kC(const float* __restrict__ sc,
                                          const float* __restrict__ of) {
    __shared__ float rs[8][AF];
    __shared__ float rq[8][AF];
    __shared__ int sLast;
    int t = threadIdx.x;
    int j = t & 31;
    int w = t >> 5;
    int a = blockIdx.x * 8 + w;
    int c0 = 2 * j;

    float2 G1A = *(const float2*)&d_g1[c0];      float2 H1A = *(const float2*)&d_h1[c0];
    float2 G1B = *(const float2*)&d_g1[64 + c0]; float2 H1B = *(const float2*)&d_h1[64 + c0];

    const float* gp = d_gated + (size_t)a * MNBR * TWOA;
    float s0 = 0.0f, s1 = 0.0f;
    #pragma unroll
    for (int m = 0; m < MNBR; m++) {
        const float* row = gp + m * TWOA;
        float2 f = __ldcs((const float2*)(row + c0));
        float2 c = __ldcs((const float2*)(row + 64 + c0));
        float xf0 = f.x * G1A.x + H1A.x;
        float xf1 = f.y * G1A.y + H1A.y;
        float xc0 = c.x * G1B.x + H1B.x;
        float xc1 = c.y * G1B.y + H1B.y;
        s0 += sigmoidf_(xf0) * softplusf_(xc0);
        s1 += sigmoidf_(xf1) * softplusf_(xc1);
    }
    float2 sv; sv.x = s0; sv.y = s1;
    *(float2*)&d_summed[(size_t)a * AF + c0] = sv;

    rs[w][c0] = s0;       rq[w][c0] = s0 * s0;
    rs[w][c0 + 1] = s1;   rq[w][c0 + 1] = s1 * s1;
    __syncthreads();
    if (t < AF) {
        float s = 0.0f, q = 0.0f;
        #pragma unroll
        for (int w2 = 0; w2 < 8; w2++) { s += rs[w2][t]; q += rq[w2][t]; }
        atomicAdd(&d_s2[t], (double)s);
        atomicAdd(&d_q2[t], (double)q);
    }
    __syncthreads();
    if (t == 0) {
        __threadfence();
        unsigned old = atomicAdd(&d_c2, 1u);
        sLast = (old == NATOM / 8 - 1) ? 1 : 0;
    }
    __syncthreads();
    if (sLast && t < AF) {
        double s = *((volatile double*)&d_s2[t]);
        double q = *((volatile double*)&d_q2[t]);
        double mean = s / NF;
        double var  = q / NF - mean * mean;
        float g = sc[t] * (float)(1.0 / sqrt(var + EPSBN));
        d_g2[t] = g;
        d_h2[t] = of[t] - (float)mean * g;
    }
}

// ---------------- kD: out = softplus(atom + BN2(summed)) ----------------
__global__ void __launch_bounds__(256) kD(const float* __restrict__ atom,
                                          float* __restrict__ out) {
    int i = blockIdx.x * 256 + threadIdx.x;
    int c = i & (AF - 1);
    float y = d_summed[i] * d_g2[c] + d_h2[c];
    out[i] = softplusf_(atom[i] + y);
}

// ---------------- launch ----------------
extern "C" void kernel_launch(void* const* d_in, const int* in_sizes, int n_in,
                              void* d_out, int out_size) {
    const int*   nidx = (const int*)  d_in[0];
    const float* atom = (const float*)d_in[1];
    const float* bond = (const float*)d_in[2];
    const float* W    = (const float*)d_in[3];
    const float* bias = (const float*)d_in[4];
    const float* bn1s = (const float*)d_in[5];
    const float* bn1o = (const float*)d_in[6];
    const float* bn2s = (const float*)d_in[7];
    const float* bn2o = (const float*)d_in[8];
    float* out = (float*)d_out;

    cudaFuncSetAttribute(kGemmStore, cudaFuncAttributeMaxDynamicSharedMemorySize, SMEM_BYTES);

    kInitA<<<1, 128>>>();                                                    // slot 1
    kA<<<(NATOM + 127) / 128, 256>>>(atom, W, bias);                         // slot 2
    kInitB<<<1, 64>>>();                                                     // slot 3
    kGemmStore<<<GEMM_GRID, 384, SMEM_BYTES>>>(bond, nidx, W, bn1s, bn1o);   // slot 4 (ncu)
    kC<<<NATOM / 8, 256>>>(bn2s, bn2o);                                      // slot 5
    kD<<<(NATOM * AF) / 256, 256>>>(atom, out);                              // slot 6
}

// round 8
// speedup vs baseline: 1.2130x; 1.2130x over previous
#include <cuda_runtime.h>
#include <cuda_fp16.h>

#define NATOM 100000
#define MNBR  12
#define AF    64
#define BF    41
#define TWOA  128
#define NM    (NATOM*MNBR)          // 1200000
#define NMF   ((double)NM)
#define NF    ((double)NATOM)
#define EPSBN 1e-5
#define GEMM_GRID (NM/96)           // 12500

// ---- dynamic smem layout (bytes) ----
#define BT_PAD    104
#define OFF_WS    0                              // float Ws[41][128] raw W3 = 20992
#define OFF_BT    20992                          // float bT[41][104]       = 17056
#define OFF_BRAW  (OFF_BT + BF*BT_PAD*4)         // 38048; float braw[96*41]= 15744
#define OFF_SWS   (OFF_BRAW + 96*BF*4)           // 53792; float SWs[8*128] = 4096
#define OFF_IDX   (OFF_SWS + 8*TWOA*4)           // 57888; int idxS[96]
#define SMEM_BYTES (OFF_IDX + 96*4)              // 58272  (x2 = 116.5 KB)
#define OFF_RED   OFF_BRAW                       // reductions overlay braw (dead post-transpose)

typedef unsigned long long ull;

// ---------------- scratch (device globals; no allocations) ----------------
__device__ float  d_SW[(size_t)NATOM*TWOA];      // atom @ W[0:64] + bias
__device__ float  d_PW[(size_t)NATOM*TWOA];      // atom @ W[64:128]
__device__ ull    d_gated16[(size_t)NM*32];      // fp16 gated, row = 32 ull (307 MB)
__device__ float  d_summed[(size_t)NATOM*AF];
__device__ double d_s1[TWOA], d_q1[TWOA];
__device__ double d_s2[AF],   d_q2[AF];
__device__ float  d_g1[TWOA], d_h1[TWOA];
__device__ float  d_g2[AF],   d_h2[AF];
__device__ unsigned d_c1, d_c2;

// ---------------- helpers ----------------
__device__ __forceinline__ void ffma2(ull &d, ull a, ull b) {
    asm("fma.rn.f32x2 %0, %1, %2, %0;" : "+l"(d) : "l"(a), "l"(b));
}
__device__ __forceinline__ ull packdup(float x) {
    ull r; asm("mov.b64 %0, {%1, %1};" : "=l"(r) : "f"(x)); return r;
}
__device__ __forceinline__ float2 unpk(ull v) {
    float2 r; asm("mov.b64 {%0, %1}, %2;" : "=f"(r.x), "=f"(r.y) : "l"(v)); return r;
}
__device__ __forceinline__ float sigmoidf_(float x) {
    return __fdividef(1.0f, 1.0f + __expf(-x));
}
__device__ __forceinline__ float softplusf_(float x) {
    float e = __expf(-fabsf(x));
    return fmaxf(x, 0.0f) + __logf(1.0f + e);
}
__device__ __forceinline__ void cpasync16(void* dst_smem, const void* src) {
    unsigned s = (unsigned)__cvta_generic_to_shared(dst_smem);
    asm volatile("cp.async.cg.shared.global [%0], [%1], 16;" :: "r"(s), "l"(src) : "memory");
}
#define CP_COMMIT() asm volatile("cp.async.commit_group;" ::: "memory")
#define CP_WAIT(n)  asm volatile("cp.async.wait_group %0;" :: "n"(n) : "memory")

// ---------------- kInitA / kInitB ----------------
__global__ void kInitA() {
    int t = threadIdx.x;
    if (t < TWOA) { d_s1[t] = 0.0; d_q1[t] = 0.0; }
    if (t == 0)   d_c1 = 0u;
}
__global__ void kInitB() {
    int t = threadIdx.x;
    if (t < AF) { d_s2[t] = 0.0; d_q2[t] = 0.0; }
    if (t == 0) d_c2 = 0u;
}

// ---------------- kA: SW = atom@W1 + b, PW = atom@W2 ----------------
__global__ void __launch_bounds__(256) kA(const float* __restrict__ atom,
                                          const float* __restrict__ W,
                                          const float* __restrict__ bias) {
    __shared__ __align__(16) float at[64][132];
    int t = threadIdx.x;
    int aBase = blockIdx.x * 128;
    int aCount = NATOM - aBase; if (aCount > 128) aCount = 128;

    float wreg[64];
    const float* wp = (t < 128) ? (W + t) : (W + 64 * TWOA + (t - 128));
    #pragma unroll
    for (int k = 0; k < 64; k++) wreg[k] = wp[k * TWOA];
    float bj = (t < 128) ? bias[t] : 0.0f;

    for (int idx = t; idx < 128 * 64; idx += 256) {
        int a = idx >> 6, k = idx & 63;
        at[k][a] = (a < aCount) ? atom[(size_t)(aBase + a) * AF + k] : 0.0f;
    }
    __syncthreads();

    float* dst = (t < 128) ? d_SW : d_PW;
    int j = t & 127;

    for (int c = 0; c < 16; c++) {
        int a0 = c * 8;
        ull acc[4] = {0ull, 0ull, 0ull, 0ull};
        #pragma unroll
        for (int k = 0; k < 64; k++) {
            ull wk = packdup(wreg[k]);
            const ull* ap = (const ull*)&at[k][a0];
            ffma2(acc[0], ap[0], wk);
            ffma2(acc[1], ap[1], wk);
            ffma2(acc[2], ap[2], wk);
            ffma2(acc[3], ap[3], wk);
        }
        #pragma unroll
        for (int q = 0; q < 4; q++) {
            float2 v = unpk(acc[q]);
            int a = a0 + 2 * q;
            if (a < aCount)     dst[(size_t)(aBase + a)     * TWOA + j] = v.x + bj;
            if (a + 1 < aCount) dst[(size_t)(aBase + a + 1) * TWOA + j] = v.y + bj;
        }
    }
}

// ============ kGemmStore: gated = bond@W3 + SW + PW_gather; fp16 store; BN1 stats ============
// block = 96 rows (8 atoms) x 128 cols, 384 threads = 12 warps, warp owns 8 rows.
// lane owns cols {2l,2l+1, 64+2l,64+2l+1}. PW gathered directly from L2 in epilogue.
__global__ void __launch_bounds__(384, 2) kGemmStore(const float* __restrict__ bond,
                                                     const int*   __restrict__ nidx,
                                                     const float* __restrict__ W,
                                                     const float* __restrict__ sc,
                                                     const float* __restrict__ of) {
    extern __shared__ __align__(16) char sm[];
    float*  Ws   = (float*) (sm + OFF_WS);
    float*  bT   = (float*) (sm + OFF_BT);
    float*  braw = (float*) (sm + OFF_BRAW);
    float*  SWs  = (float*) (sm + OFF_SWS);
    int*    idxS = (int*)   (sm + OFF_IDX);
    __shared__ int sLast;

    int t = threadIdx.x, lane = t & 31, w = t >> 5;   // w in 0..11
    int blk = blockIdx.x;
    int r0 = 8 * w;
    int cA = 2 * lane;

    // (1) group 1: bond tile raw -> smem (984 16B chunks)
    {
        const float* bsrc = bond + (size_t)blk * 96 * BF;
        #pragma unroll
        for (int i = 0; i < 3; i++) {
            int c = t + 384 * i;
            if (c < 96 * BF / 4) cpasync16(braw + c * 4, bsrc + c * 4);
        }
    }
    CP_COMMIT();

    // (2) group 2: W3 raw (1312 chunks) + SW rows (256 chunks)
    {
        const float* wsrc = W + TWOA * TWOA;
        #pragma unroll
        for (int i = 0; i < 4; i++) {
            int c = t + 384 * i;
            if (c < BF * TWOA / 4) cpasync16(Ws + c * 4, wsrc + c * 4);
        }
        if (t < 256) cpasync16(SWs + t * 4, d_SW + (size_t)blk * 8 * TWOA + t * 4);
    }
    CP_COMMIT();

    // (3) neighbor indices (needed only in epilogue; covered by later syncs)
    if (t < 96) idxS[t] = nidx[blk * 96 + t];

    // (4) wait bond; transpose braw[r][k] -> bT[k][r] (conflict-free: 41 odd stride)
    CP_WAIT(1);
    __syncthreads();
    #pragma unroll
    for (int i = 0; i < 11; i++) {
        int id = t + 384 * i;
        if (id < 96 * BF) {
            int k = id / 96, r = id - 96 * k;
            bT[k * BT_PAD + r] = braw[r * BF + k];
        }
    }
    CP_WAIT(0);
    __syncthreads();   // bT + Ws + SWs + idxS all visible

    // (5) GEMM: acc[p] = row-pair (r0+2p, r0+2p+1), 4 cols each
    ull acc[4][4];
    #pragma unroll
    for (int p = 0; p < 4; p++)
        #pragma unroll
        for (int u = 0; u < 4; u++) acc[p][u] = 0ull;

    #pragma unroll
    for (int k = 0; k < BF; k++) {
        float2 wa = *(const float2*)&Ws[k * TWOA + cA];
        float2 wb = *(const float2*)&Ws[k * TWOA + 64 + cA];
        ull w0 = packdup(wa.x), w1 = packdup(wa.y);
        ull w2 = packdup(wb.x), w3 = packdup(wb.y);
        const char* brow = (const char*)(bT + k * BT_PAD + r0);
        ulonglong2 q0 = *(const ulonglong2*)(brow);
        ulonglong2 q1 = *(const ulonglong2*)(brow + 16);
        ull bv0 = q0.x, bv1 = q0.y, bv2 = q1.x, bv3 = q1.y;
        ffma2(acc[0][0], bv0, w0); ffma2(acc[0][1], bv0, w1); ffma2(acc[0][2], bv0, w2); ffma2(acc[0][3], bv0, w3);
        ffma2(acc[1][0], bv1, w0); ffma2(acc[1][1], bv1, w1); ffma2(acc[1][2], bv1, w2); ffma2(acc[1][3], bv1, w3);
        ffma2(acc[2][0], bv2, w0); ffma2(acc[2][1], bv2, w1); ffma2(acc[2][2], bv2, w2); ffma2(acc[2][3], bv2, w3);
        ffma2(acc[3][0], bv3, w0); ffma2(acc[3][1], bv3, w1); ffma2(acc[3][2], bv3, w2); ffma2(acc[3][3], bv3, w3);
    }

    // (6) epilogue: direct PW gathers from L2, assemble gated, fp16 packed store, stats
    ull* gbase = d_gated16 + (size_t)(blk * 96 + r0) * 32;

    float ls0 = 0, ls1 = 0, ls2 = 0, ls3 = 0;
    float lq0 = 0, lq1 = 0, lq2 = 0, lq3 = 0;
    #pragma unroll
    for (int p = 0; p < 4; p++) {
        float2 aA0 = unpk(acc[p][0]), aA1 = unpk(acc[p][1]);
        float2 aB0 = unpk(acc[p][2]), aB1 = unpk(acc[p][3]);
        #pragma unroll
        for (int s = 0; s < 2; s++) {
            int rr = r0 + 2 * p + s;          // local row 0..95
            int aLoc = rr / 12;               // local atom 0..7
            const float* swr = SWs + aLoc * TWOA;
            const float* pw  = d_PW + (size_t)idxS[rr] * TWOA;
            float2 swA = *(const float2*)(swr + cA);
            float2 swB = *(const float2*)(swr + 64 + cA);
            float2 pA  = __ldg((const float2*)(pw + cA));
            float2 pB  = __ldg((const float2*)(pw + 64 + cA));
            float v0 = (s ? aA0.y : aA0.x) + swA.x + pA.x;
            float v1 = (s ? aA1.y : aA1.x) + swA.y + pA.y;
            float v2 = (s ? aB0.y : aB0.x) + swB.x + pB.x;
            float v3 = (s ? aB1.y : aB1.x) + swB.y + pB.y;
            __half2 hA = __floats2half2_rn(v0, v1);
            __half2 hB = __floats2half2_rn(v2, v3);
            unsigned uA = *(unsigned*)&hA;
            unsigned uB = *(unsigned*)&hB;
            ull pk = (ull)uA | ((ull)uB << 32);
            __stcs(gbase + (size_t)(2 * p + s) * 32 + lane, pk);
            ls0 += v0; lq0 += v0 * v0;
            ls1 += v1; lq1 += v1 * v1;
            ls2 += v2; lq2 += v2 * v2;
            ls3 += v3; lq3 += v3 * v3;
        }
    }
    float* redS = (float*)(sm + OFF_RED);
    float* redQ = redS + 12 * TWOA;              // overlays braw region (dead)
    redS[w * TWOA + cA] = ls0;       redS[w * TWOA + cA + 1] = ls1;
    redS[w * TWOA + 64 + cA] = ls2;  redS[w * TWOA + 64 + cA + 1] = ls3;
    redQ[w * TWOA + cA] = lq0;       redQ[w * TWOA + cA + 1] = lq1;
    redQ[w * TWOA + 64 + cA] = lq2;  redQ[w * TWOA + 64 + cA + 1] = lq3;
    __syncthreads();
    if (t < TWOA) {
        float s = 0.0f, q = 0.0f;
        #pragma unroll
        for (int w2 = 0; w2 < 12; w2++) { s += redS[w2 * TWOA + t]; q += redQ[w2 * TWOA + t]; }
        atomicAdd(&d_s1[t], (double)s);
        atomicAdd(&d_q1[t], (double)q);
    }
    __syncthreads();
    if (t == 0) {
        __threadfence();
        unsigned old = atomicAdd(&d_c1, 1u);
        sLast = (old == GEMM_GRID - 1) ? 1 : 0;
    }
    __syncthreads();
    if (sLast && t < TWOA) {
        double s = *((volatile double*)&d_s1[t]);
        double q = *((volatile double*)&d_q1[t]);
        double mean = s / NMF;
        double var  = q / NMF - mean * mean;
        float g = sc[t] * (float)(1.0 / sqrt(var + EPSBN));
        d_g1[t] = g;
        d_h1[t] = of[t] - (float)mean * g;
    }
}

// ---------------- kC: stream fp16 gated -> BN1 affine -> sig*softplus -> sum_M; BN2 stats ----
// block = 8 warps = 8 atoms; lane j owns output cols 2j, 2j+1
__global__ void __launch_bounds__(256) kC(const float* __restrict__ sc,
                                          const float* __restrict__ of) {
    __shared__ float rs[8][AF];
    __shared__ float rq[8][AF];
    __shared__ int sLast;
    int t = threadIdx.x;
    int j = t & 31;
    int w = t >> 5;
    int a = blockIdx.x * 8 + w;
    int c0 = 2 * j;

    float2 G1A = *(const float2*)&d_g1[c0];      float2 H1A = *(const float2*)&d_h1[c0];
    float2 G1B = *(const float2*)&d_g1[64 + c0]; float2 H1B = *(const float2*)&d_h1[64 + c0];

    const ull* gp = d_gated16 + (size_t)a * MNBR * 32;
    float s0 = 0.0f, s1 = 0.0f;
    #pragma unroll
    for (int m = 0; m < MNBR; m++) {
        ull u = __ldcs(gp + m * 32 + j);
        unsigned lo = (unsigned)u, hi = (unsigned)(u >> 32);
        float2 f = __half22float2(*(__half2*)&lo);
        float2 c = __half22float2(*(__half2*)&hi);
        float xf0 = f.x * G1A.x + H1A.x;
        float xf1 = f.y * G1A.y + H1A.y;
        float xc0 = c.x * G1B.x + H1B.x;
        float xc1 = c.y * G1B.y + H1B.y;
        s0 += sigmoidf_(xf0) * softplusf_(xc0);
        s1 += sigmoidf_(xf1) * softplusf_(xc1);
    }
    float2 sv; sv.x = s0; sv.y = s1;
    *(float2*)&d_summed[(size_t)a * AF + c0] = sv;

    rs[w][c0] = s0;       rq[w][c0] = s0 * s0;
    rs[w][c0 + 1] = s1;   rq[w][c0 + 1] = s1 * s1;
    __syncthreads();
    if (t < AF) {
        float s = 0.0f, q = 0.0f;
        #pragma unroll
        for (int w2 = 0; w2 < 8; w2++) { s += rs[w2][t]; q += rq[w2][t]; }
        atomicAdd(&d_s2[t], (double)s);
        atomicAdd(&d_q2[t], (double)q);
    }
    __syncthreads();
    if (t == 0) {
        __threadfence();
        unsigned old = atomicAdd(&d_c2, 1u);
        sLast = (old == NATOM / 8 - 1) ? 1 : 0;
    }
    __syncthreads();
    if (sLast && t < AF) {
        double s = *((volatile double*)&d_s2[t]);
        double q = *((volatile double*)&d_q2[t]);
        double mean = s / NF;
        double var  = q / NF - mean * mean;
        float g = sc[t] * (float)(1.0 / sqrt(var + EPSBN));
        d_g2[t] = g;
        d_h2[t] = of[t] - (float)mean * g;
    }
}

// ---------------- kD: out = softplus(atom + BN2(summed)) ----------------
__global__ void __launch_bounds__(256) kD(const float* __restrict__ atom,
                                          float* __restrict__ out) {
    int i = blockIdx.x * 256 + threadIdx.x;
    int c = i & (AF - 1);
    float y = d_summed[i] * d_g2[c] + d_h2[c];
    out[i] = softplusf_(atom[i] + y);
}

// ---------------- launch ----------------
extern "C" void kernel_launch(void* const* d_in, const int* in_sizes, int n_in,
                              void* d_out, int out_size) {
    const int*   nidx = (const int*)  d_in[0];
    const float* atom = (const float*)d_in[1];
    const float* bond = (const float*)d_in[2];
    const float* W    = (const float*)d_in[3];
    const float* bias = (const float*)d_in[4];
    const float* bn1s = (const float*)d_in[5];
    const float* bn1o = (const float*)d_in[6];
    const float* bn2s = (const float*)d_in[7];
    const float* bn2o = (const float*)d_in[8];
    float* out = (float*)d_out;

    cudaFuncSetAttribute(kGemmStore, cudaFuncAttributeMaxDynamicSharedMemorySize, SMEM_BYTES);

    kInitA<<<1, 128>>>();                                                    // slot 1
    kA<<<(NATOM + 127) / 128, 256>>>(atom, W, bias);                         // slot 2
    kInitB<<<1, 64>>>();                                                     // slot 3
    kGemmStore<<<GEMM_GRID, 384, SMEM_BYTES>>>(bond, nidx, W, bn1s, bn1o);   // slot 4 (ncu)
    kC<<<NATOM / 8, 256>>>(bn2s, bn2o);                                      // slot 5
    kD<<<(NATOM * AF) / 256, 256>>>(atom, out);                              // slot 6
}